// round 5
// baseline (speedup 1.0000x reference)
#include <cuda_runtime.h>

#define BATCH 1024
#define SEQ   512
#define EDIM  300
#define HDIM  512
#define ODIM  5
#define E4    (EDIM / 4)

// Device scratch (allocation-free rule)
__device__ __align__(16) float g_y[BATCH * EDIM];     // pooled embeddings
__device__ __align__(16) float g_w1T[EDIM * HDIM];    // w1 transposed [E][H]
__device__ __align__(16) float g_h[BATCH * HDIM];     // hidden activations

// ---------------------------------------------------------------------------
// Kernel A: per-batch-row embedding gather + sum + length + divide.
// ---------------------------------------------------------------------------
__global__ __launch_bounds__(96) void gather_mean_kernel(
    const int* __restrict__ x,
    const float* __restrict__ weight)
{
    __shared__ int xs[SEQ];
    __shared__ int firstZero;

    const int b   = blockIdx.x;
    const int tid = threadIdx.x;

    if (tid == 0) firstZero = SEQ;
    __syncthreads();

    const int* xrow = x + b * SEQ;
    for (int l = tid; l < SEQ; l += 96) {
        int t = __ldg(xrow + l);
        xs[l] = t;
        if (t == 0) atomicMin(&firstZero, l);
    }
    __syncthreads();

    const float len = (xs[SEQ - 1] != 0) ? (float)SEQ : (float)firstZero;

    if (tid < E4) {
        float4 acc = make_float4(0.f, 0.f, 0.f, 0.f);
        #pragma unroll 8
        for (int l = 0; l < SEQ; ++l) {
            const float4* row4 =
                reinterpret_cast<const float4*>(weight + (size_t)xs[l] * EDIM);
            const float4 v = __ldg(row4 + tid);
            acc.x += v.x; acc.y += v.y; acc.z += v.z; acc.w += v.w;
        }
        const float inv = 1.0f / len;
        acc.x *= inv; acc.y *= inv; acc.z *= inv; acc.w *= inv;
        reinterpret_cast<float4*>(g_y + (size_t)b * EDIM)[tid] = acc;
    }
}

// ---------------------------------------------------------------------------
// Kernel T: transpose w1 [H,E] -> g_w1T [E,H] (coalesced writes).
// ---------------------------------------------------------------------------
__global__ __launch_bounds__(256) void transpose_w1_kernel(const float* __restrict__ w1)
{
    int idx = blockIdx.x * 256 + threadIdx.x;   // grid covers EDIM*HDIM exactly
    int e = idx / HDIM;
    int j = idx % HDIM;
    g_w1T[idx] = __ldg(w1 + j * EDIM + e);
}

// ---------------------------------------------------------------------------
// Kernel B1: GEMM1  h = relu(y @ w1^T + b1)  via w1T + packed f32x2 FMA.
// Block: 64 threads (2 warps). Block covers 8 batch rows x 256 hidden.
// Warp w: hidden chunk [blockIdx.y*256 + w*128, +128), lane owns 4 hidden.
// y for 8 rows packed as float2 row-pairs in smem; LDS.64 broadcast.
// Each thread: 4 hidden x 4 row-pairs = 16 b64 accumulators.
// ---------------------------------------------------------------------------
#define G1_ROWS 8

__device__ __forceinline__ unsigned long long dup_f32(float w) {
    unsigned long long r;
    asm("mov.b64 %0, {%1, %1};" : "=l"(r) : "f"(w));
    return r;
}
#define FMA2(acc, a, b) \
    asm("fma.rn.f32x2 %0, %1, %2, %0;" : "+l"(acc) : "l"(a), "l"(b))

__global__ __launch_bounds__(64) void gemm1_kernel(const float* __restrict__ b1)
{
    __shared__ __align__(8) float2 ys2[G1_ROWS / 2][EDIM];   // 9.6 KB

    const int tid  = threadIdx.x;
    const int w    = tid >> 5;
    const int lane = tid & 31;
    const int b0   = blockIdx.x * G1_ROWS;

    // stage y rows packed as pairs: ys2[r/2][e] = {y[2rp][e], y[2rp+1][e]}
    for (int i = tid; i < G1_ROWS * EDIM; i += 64) {
        int r = i / EDIM, e = i % EDIM;
        ((float*)&ys2[r >> 1][e])[r & 1] = g_y[(size_t)(b0 + r) * EDIM + e];
    }
    __syncthreads();

    const int j4 = blockIdx.y * 64 + w * 32 + lane;          // float4 col index
    const float4* w1T4 = reinterpret_cast<const float4*>(g_w1T);
    const unsigned long long* ysu =
        reinterpret_cast<const unsigned long long*>(ys2);    // [rp*EDIM + e]

    unsigned long long acc[4][4] = {};   // [j within float4][row pair]

    #pragma unroll 4
    for (int e = 0; e < EDIM; ++e) {
        const float4 wv = __ldg(w1T4 + e * (HDIM / 4) + j4);
        const unsigned long long wd0 = dup_f32(wv.x);
        const unsigned long long wd1 = dup_f32(wv.y);
        const unsigned long long wd2 = dup_f32(wv.z);
        const unsigned long long wd3 = dup_f32(wv.w);
        #pragma unroll
        for (int rp = 0; rp < 4; ++rp) {
            const unsigned long long yv = ysu[rp * EDIM + e];  // LDS.64 broadcast
            FMA2(acc[0][rp], wd0, yv);
            FMA2(acc[1][rp], wd1, yv);
            FMA2(acc[2][rp], wd2, yv);
            FMA2(acc[3][rp], wd3, yv);
        }
    }

    // epilogue: bias + relu, scatter to g_h
    const int jbase = j4 * 4;
    #pragma unroll
    for (int j = 0; j < 4; ++j) {
        const float bj = __ldg(b1 + jbase + j);
        #pragma unroll
        for (int rp = 0; rp < 4; ++rp) {
            const float lo = __uint_as_float((unsigned)(acc[j][rp] & 0xffffffffull));
            const float hi = __uint_as_float((unsigned)(acc[j][rp] >> 32));
            g_h[(size_t)(b0 + 2 * rp)     * HDIM + jbase + j] = fmaxf(lo + bj, 0.f);
            g_h[(size_t)(b0 + 2 * rp + 1) * HDIM + jbase + j] = fmaxf(hi + bj, 0.f);
        }
    }
}

// ---------------------------------------------------------------------------
// Kernel B2: GEMM2  out = h @ w2^T + b2.  One warp per batch row.
// ---------------------------------------------------------------------------
__global__ __launch_bounds__(256) void gemm2_kernel(
    const float* __restrict__ w2,
    const float* __restrict__ b2,
    float* __restrict__ out)
{
    const int w    = threadIdx.x >> 5;
    const int lane = threadIdx.x & 31;
    const int r    = blockIdx.x * 8 + w;

    const float4* h4  = reinterpret_cast<const float4*>(g_h + (size_t)r * HDIM);
    const float4* w24 = reinterpret_cast<const float4*>(w2);

    float s[ODIM] = {0.f, 0.f, 0.f, 0.f, 0.f};
    #pragma unroll
    for (int i = 0; i < 4; ++i) {
        const float4 hv = h4[lane + i * 32];
        #pragma unroll
        for (int o = 0; o < ODIM; ++o) {
            const float4 wv = __ldg(w24 + o * (HDIM / 4) + lane + i * 32);
            s[o] += hv.x * wv.x + hv.y * wv.y + hv.z * wv.z + hv.w * wv.w;
        }
    }
    #pragma unroll
    for (int o = 0; o < ODIM; ++o) {
        #pragma unroll
        for (int off = 16; off > 0; off >>= 1)
            s[o] += __shfl_down_sync(0xffffffffu, s[o], off);
    }
    if (lane == 0) {
        #pragma unroll
        for (int o = 0; o < ODIM; ++o)
            out[(size_t)r * ODIM + o] = s[o] + __ldg(b2 + o);
    }
}

// ---------------------------------------------------------------------------
extern "C" void kernel_launch(void* const* d_in, const int* in_sizes, int n_in,
                              void* d_out, int out_size)
{
    const int*   x      = (const int*)d_in[0];
    const float* weight = (const float*)d_in[1];
    const float* w1     = (const float*)d_in[2];
    const float* b1     = (const float*)d_in[3];
    const float* w2     = (const float*)d_in[4];
    const float* b2     = (const float*)d_in[5];
    float*       out    = (float*)d_out;

    transpose_w1_kernel<<<(EDIM * HDIM) / 256, 256>>>(w1);
    gather_mean_kernel<<<BATCH, 96>>>(x, weight);
    gemm1_kernel<<<dim3(BATCH / G1_ROWS, 2), 64>>>(b1);
    gemm2_kernel<<<BATCH / 8, 256>>>(w2, b2, out);
}

// round 7
// speedup vs baseline: 1.2316x; 1.2316x over previous
#include <cuda_runtime.h>

#define BATCH 1024
#define SEQ   512
#define EDIM  300
#define HDIM  512
#define ODIM  5
#define E4    (EDIM / 4)

typedef unsigned long long u64;

// Device scratch (allocation-free rule)
__device__ __align__(16) float g_y[BATCH * EDIM];     // pooled embeddings
__device__ __align__(16) float g_w1T[EDIM * HDIM];    // w1 transposed [E][H]

// ---------------------------------------------------------------------------
// Kernel A: per-batch-row embedding gather + sum + length + divide.
// One block per batch row, 96 threads; threads 0..74 own one float4 slot.
// ---------------------------------------------------------------------------
__global__ __launch_bounds__(96) void gather_mean_kernel(
    const int* __restrict__ x,
    const float* __restrict__ weight)
{
    __shared__ int xs[SEQ];
    __shared__ int firstZero;

    const int b   = blockIdx.x;
    const int tid = threadIdx.x;

    if (tid == 0) firstZero = SEQ;
    __syncthreads();

    const int* xrow = x + b * SEQ;
    for (int l = tid; l < SEQ; l += 96) {
        int t = __ldg(xrow + l);
        xs[l] = t;
        if (t == 0) atomicMin(&firstZero, l);
    }
    __syncthreads();

    const float len = (xs[SEQ - 1] != 0) ? (float)SEQ : (float)firstZero;

    if (tid < E4) {
        float4 acc = make_float4(0.f, 0.f, 0.f, 0.f);
        #pragma unroll 8
        for (int l = 0; l < SEQ; ++l) {
            const float4* row4 =
                reinterpret_cast<const float4*>(weight + (size_t)xs[l] * EDIM);
            const float4 v = __ldg(row4 + tid);
            acc.x += v.x; acc.y += v.y; acc.z += v.z; acc.w += v.w;
        }
        const float inv = 1.0f / len;
        acc.x *= inv; acc.y *= inv; acc.z *= inv; acc.w *= inv;
        reinterpret_cast<float4*>(g_y + (size_t)b * EDIM)[tid] = acc;
    }
}

// ---------------------------------------------------------------------------
// Kernel T: transpose w1 [H,E] -> g_w1T [E,H]. Coalesced reads (along E),
// scattered stores (stores don't stall; total sector traffic ~5 MB).
// ---------------------------------------------------------------------------
__global__ __launch_bounds__(256) void transpose_w1_kernel(const float* __restrict__ w1)
{
    int idx = blockIdx.x * 256 + threadIdx.x;   // covers HDIM*EDIM exactly
    int j = idx / EDIM;        // hidden row (source row-major)
    int e = idx % EDIM;
    g_w1T[e * HDIM + j] = __ldg(w1 + idx);
}

// ---------------------------------------------------------------------------
// Kernel B: fused MLP (R3 shape, fixed memory pattern).
// grid=128, 256 threads. Block covers 8 batch rows, full hidden dim.
// Thread owns hidden units 2*tid, 2*tid+1. Per e: coalesced LDG.64 of w1T,
// 4x LDS.64 broadcast of y row-pairs, 8x FFMA2 (fma.rn.f32x2).
// Then gemm2: warp r reduces row r over HDIM for the 5 outputs.
// ---------------------------------------------------------------------------
#define ROWS 8

__device__ __forceinline__ u64 dup_f32(float w) {
    u64 r;
    asm("mov.b64 %0, {%1, %1};" : "=l"(r) : "f"(w));
    return r;
}
#define FMA2(acc, a, b) \
    asm("fma.rn.f32x2 %0, %1, %2, %0;" : "+l"(acc) : "l"(a), "l"(b))

__global__ __launch_bounds__(256) void mlp_kernel(
    const float* __restrict__ b1,
    const float* __restrict__ w2,
    const float* __restrict__ b2,
    float* __restrict__ out)
{
    __shared__ __align__(16) u64 ys2[EDIM][ROWS / 2];   // [e][rowpair], 9.6 KB
    __shared__ float hs[ROWS][HDIM];                    // 16 KB

    const int tid = threadIdx.x;
    const int b0  = blockIdx.x * ROWS;

    // stage y: ys2[e][rp] = {y[b0+2rp][e], y[b0+2rp+1][e]}
    for (int i = tid; i < EDIM * ROWS; i += 256) {
        int e = i / ROWS, r = i % ROWS;
        ((float*)&ys2[e][r >> 1])[r & 1] = g_y[(size_t)(b0 + r) * EDIM + e];
    }
    __syncthreads();

    // ---- GEMM1
    const float2* w1T2 = reinterpret_cast<const float2*>(g_w1T);
    u64 acc[2][4] = {};   // [j in pair][row pair]

    #pragma unroll 4
    for (int e = 0; e < EDIM; ++e) {
        const float2 wv = __ldg(w1T2 + e * (HDIM / 2) + tid);   // coalesced
        const u64 wd0 = dup_f32(wv.x);
        const u64 wd1 = dup_f32(wv.y);
        #pragma unroll
        for (int rp = 0; rp < 4; ++rp) {
            const u64 yv = ys2[e][rp];                          // LDS.64 broadcast
            FMA2(acc[0][rp], wd0, yv);
            FMA2(acc[1][rp], wd1, yv);
        }
    }

    const int j0 = tid * 2;
    const float bj0 = __ldg(b1 + j0);
    const float bj1 = __ldg(b1 + j0 + 1);
    #pragma unroll
    for (int rp = 0; rp < 4; ++rp) {
        const float lo0 = __uint_as_float((unsigned)(acc[0][rp] & 0xffffffffull));
        const float hi0 = __uint_as_float((unsigned)(acc[0][rp] >> 32));
        const float lo1 = __uint_as_float((unsigned)(acc[1][rp] & 0xffffffffull));
        const float hi1 = __uint_as_float((unsigned)(acc[1][rp] >> 32));
        hs[2 * rp    ][j0]     = fmaxf(lo0 + bj0, 0.f);
        hs[2 * rp + 1][j0]     = fmaxf(hi0 + bj0, 0.f);
        hs[2 * rp    ][j0 + 1] = fmaxf(lo1 + bj1, 0.f);
        hs[2 * rp + 1][j0 + 1] = fmaxf(hi1 + bj1, 0.f);
    }
    __syncthreads();

    // ---- GEMM2: warp r handles batch row r
    const int warp = tid >> 5;
    const int lane = tid & 31;
    const float4* w24 = reinterpret_cast<const float4*>(w2);
    const float4* hrow4 = reinterpret_cast<const float4*>(&hs[warp][0]);

    float s[ODIM] = {0.f, 0.f, 0.f, 0.f, 0.f};
    #pragma unroll
    for (int i = 0; i < 4; ++i) {
        const float4 hv = hrow4[lane + i * 32];
        #pragma unroll
        for (int o = 0; o < ODIM; ++o) {
            const float4 wv = __ldg(w24 + o * (HDIM / 4) + lane + i * 32);
            s[o] += hv.x * wv.x + hv.y * wv.y + hv.z * wv.z + hv.w * wv.w;
        }
    }
    #pragma unroll
    for (int o = 0; o < ODIM; ++o) {
        #pragma unroll
        for (int off = 16; off > 0; off >>= 1)
            s[o] += __shfl_down_sync(0xffffffffu, s[o], off);
    }
    if (lane == 0) {
        #pragma unroll
        for (int o = 0; o < ODIM; ++o)
            out[(size_t)(b0 + warp) * ODIM + o] = s[o] + __ldg(b2 + o);
    }
}

// ---------------------------------------------------------------------------
extern "C" void kernel_launch(void* const* d_in, const int* in_sizes, int n_in,
                              void* d_out, int out_size)
{
    const int*   x      = (const int*)d_in[0];
    const float* weight = (const float*)d_in[1];
    const float* w1     = (const float*)d_in[2];
    const float* b1     = (const float*)d_in[3];
    const float* w2     = (const float*)d_in[4];
    const float* b2     = (const float*)d_in[5];
    float*       out    = (float*)d_out;

    transpose_w1_kernel<<<(HDIM * EDIM) / 256, 256>>>(w1);
    gather_mean_kernel<<<BATCH, 96>>>(x, weight);
    mlp_kernel<<<BATCH / ROWS, 256>>>(b1, w2, b2, out);
}

// round 8
// speedup vs baseline: 1.3888x; 1.1276x over previous
#include <cuda_runtime.h>

#define BATCH 1024
#define SEQ   512
#define EDIM  300
#define HDIM  512
#define ODIM  5
#define E4    (EDIM / 4)

typedef unsigned long long u64;

// Device scratch (allocation-free rule)
__device__ __align__(16) float g_y[BATCH * EDIM];     // pooled embeddings
__device__ __align__(16) float g_w1T[EDIM * HDIM];    // w1 transposed [E][H]

// ---------------------------------------------------------------------------
// Kernel A: per-batch-row embedding gather + sum + length + divide.
// ---------------------------------------------------------------------------
__global__ __launch_bounds__(96) void gather_mean_kernel(
    const int* __restrict__ x,
    const float* __restrict__ weight)
{
    __shared__ int xs[SEQ];
    __shared__ int firstZero;

    const int b   = blockIdx.x;
    const int tid = threadIdx.x;

    if (tid == 0) firstZero = SEQ;
    __syncthreads();

    const int* xrow = x + b * SEQ;
    for (int l = tid; l < SEQ; l += 96) {
        int t = __ldg(xrow + l);
        xs[l] = t;
        if (t == 0) atomicMin(&firstZero, l);
    }
    __syncthreads();

    const float len = (xs[SEQ - 1] != 0) ? (float)SEQ : (float)firstZero;

    if (tid < E4) {
        float4 acc = make_float4(0.f, 0.f, 0.f, 0.f);
        #pragma unroll 16
        for (int l = 0; l < SEQ; ++l) {
            const float4* row4 =
                reinterpret_cast<const float4*>(weight + (size_t)xs[l] * EDIM);
            const float4 v = __ldg(row4 + tid);
            acc.x += v.x; acc.y += v.y; acc.z += v.z; acc.w += v.w;
        }
        const float inv = 1.0f / len;
        acc.x *= inv; acc.y *= inv; acc.z *= inv; acc.w *= inv;
        reinterpret_cast<float4*>(g_y + (size_t)b * EDIM)[tid] = acc;
    }
}

// ---------------------------------------------------------------------------
// Kernel T: tiled transpose w1 [H,E] -> g_w1T [E,H], coalesced both sides.
// 32x32 tiles, 32x8 threads, padded smem. grid (10 e-tiles, 16 j-tiles).
// ---------------------------------------------------------------------------
__global__ __launch_bounds__(256) void transpose_w1_kernel(const float* __restrict__ w1)
{
    __shared__ float tile[32][33];
    const int tx = threadIdx.x;        // 0..31
    const int ty = threadIdx.y;        // 0..7
    const int e0 = blockIdx.x * 32;
    const int j0 = blockIdx.y * 32;

    #pragma unroll
    for (int k = 0; k < 4; ++k) {
        int e = e0 + tx;
        int j = j0 + ty + 8 * k;
        if (e < EDIM)
            tile[ty + 8 * k][tx] = __ldg(w1 + (size_t)j * EDIM + e);
    }
    __syncthreads();

    #pragma unroll
    for (int k = 0; k < 4; ++k) {
        int e = e0 + ty + 8 * k;
        int j = j0 + tx;
        if (e < EDIM)
            g_w1T[(size_t)e * HDIM + j] = tile[tx][ty + 8 * k];
    }
}

// ---------------------------------------------------------------------------
// Kernel B: fused MLP. grid=128, 256 threads, 8 batch rows per block.
// Thread owns hidden units 2*tid, 2*tid+1.
// Inner loop: software-pipelined w1T loads (chunks of 10 -> 10 LDGs in
// flight), y as packed row-pairs (2x LDS.128 per e), 8x FFMA2 per e.
// Then gemm2: warp r reduces row r over HDIM for the 5 outputs.
// ---------------------------------------------------------------------------
#define ROWS   8
#define ECHUNK 10          // 300 = 30 * 10

__device__ __forceinline__ u64 dup_f32(float w) {
    u64 r;
    asm("mov.b64 %0, {%1, %1};" : "=l"(r) : "f"(w));
    return r;
}
#define FMA2(acc, a, b) \
    asm("fma.rn.f32x2 %0, %1, %2, %0;" : "+l"(acc) : "l"(a), "l"(b))

__global__ __launch_bounds__(256) void mlp_kernel(
    const float* __restrict__ b1,
    const float* __restrict__ w2,
    const float* __restrict__ b2,
    float* __restrict__ out)
{
    __shared__ __align__(16) u64 ys2[EDIM][4];   // [e][rowpair], 32B per e, 9.6 KB
    __shared__ float hs[ROWS][HDIM];             // 16 KB

    const int tid = threadIdx.x;
    const int b0  = blockIdx.x * ROWS;

    // stage y: ys2[e][rp] = {y[b0+2rp][e], y[b0+2rp+1][e]}
    // i maps r=i/EDIM, e=i%EDIM -> coalesced g_y reads
    for (int i = tid; i < ROWS * EDIM; i += 256) {
        int r = i / EDIM, e = i % EDIM;
        ((float*)&ys2[e][r >> 1])[r & 1] = g_y[(size_t)(b0 + r) * EDIM + e];
    }
    __syncthreads();

    // ---- GEMM1, software-pipelined over e-chunks
    const float2* w1T2 = reinterpret_cast<const float2*>(g_w1T) + tid;
    u64 acc[2][4] = {};   // [j in pair][row pair]

    float2 wbuf[2][ECHUNK];
    #pragma unroll
    for (int k = 0; k < ECHUNK; ++k)
        wbuf[0][k] = __ldg(w1T2 + k * (HDIM / 2));

    #pragma unroll 1
    for (int g = 0; g < EDIM / ECHUNK; ++g) {
        const int cur = g & 1;
        // prefetch next chunk
        if (g + 1 < EDIM / ECHUNK) {
            const float2* src = w1T2 + (g + 1) * ECHUNK * (HDIM / 2);
            #pragma unroll
            for (int k = 0; k < ECHUNK; ++k)
                wbuf[cur ^ 1][k] = __ldg(src + k * (HDIM / 2));
        }
        // compute current chunk
        const int ebase = g * ECHUNK;
        #pragma unroll
        for (int k = 0; k < ECHUNK; ++k) {
            const ulonglong2 q0 =
                *reinterpret_cast<const ulonglong2*>(&ys2[ebase + k][0]);
            const ulonglong2 q1 =
                *reinterpret_cast<const ulonglong2*>(&ys2[ebase + k][2]);
            const u64 wd0 = dup_f32(wbuf[cur][k].x);
            const u64 wd1 = dup_f32(wbuf[cur][k].y);
            FMA2(acc[0][0], wd0, q0.x);
            FMA2(acc[0][1], wd0, q0.y);
            FMA2(acc[0][2], wd0, q1.x);
            FMA2(acc[0][3], wd0, q1.y);
            FMA2(acc[1][0], wd1, q0.x);
            FMA2(acc[1][1], wd1, q0.y);
            FMA2(acc[1][2], wd1, q1.x);
            FMA2(acc[1][3], wd1, q1.y);
        }
    }

    const int j0 = tid * 2;
    const float bj0 = __ldg(b1 + j0);
    const float bj1 = __ldg(b1 + j0 + 1);
    #pragma unroll
    for (int rp = 0; rp < 4; ++rp) {
        const float lo0 = __uint_as_float((unsigned)(acc[0][rp] & 0xffffffffull));
        const float hi0 = __uint_as_float((unsigned)(acc[0][rp] >> 32));
        const float lo1 = __uint_as_float((unsigned)(acc[1][rp] & 0xffffffffull));
        const float hi1 = __uint_as_float((unsigned)(acc[1][rp] >> 32));
        hs[2 * rp    ][j0]     = fmaxf(lo0 + bj0, 0.f);
        hs[2 * rp + 1][j0]     = fmaxf(hi0 + bj0, 0.f);
        hs[2 * rp    ][j0 + 1] = fmaxf(lo1 + bj1, 0.f);
        hs[2 * rp + 1][j0 + 1] = fmaxf(hi1 + bj1, 0.f);
    }
    __syncthreads();

    // ---- GEMM2: warp r handles batch row r
    const int warp = tid >> 5;
    const int lane = tid & 31;
    const float4* w24 = reinterpret_cast<const float4*>(w2);
    const float4* hrow4 = reinterpret_cast<const float4*>(&hs[warp][0]);

    float s[ODIM] = {0.f, 0.f, 0.f, 0.f, 0.f};
    #pragma unroll
    for (int i = 0; i < 4; ++i) {
        const float4 hv = hrow4[lane + i * 32];
        #pragma unroll
        for (int o = 0; o < ODIM; ++o) {
            const float4 wv = __ldg(w24 + o * (HDIM / 4) + lane + i * 32);
            s[o] += hv.x * wv.x + hv.y * wv.y + hv.z * wv.z + hv.w * wv.w;
        }
    }
    #pragma unroll
    for (int o = 0; o < ODIM; ++o) {
        #pragma unroll
        for (int off = 16; off > 0; off >>= 1)
            s[o] += __shfl_down_sync(0xffffffffu, s[o], off);
    }
    if (lane == 0) {
        #pragma unroll
        for (int o = 0; o < ODIM; ++o)
            out[(size_t)(b0 + warp) * ODIM + o] = s[o] + __ldg(b2 + o);
    }
}

// ---------------------------------------------------------------------------
extern "C" void kernel_launch(void* const* d_in, const int* in_sizes, int n_in,
                              void* d_out, int out_size)
{
    const int*   x      = (const int*)d_in[0];
    const float* weight = (const float*)d_in[1];
    const float* w1     = (const float*)d_in[2];
    const float* b1     = (const float*)d_in[3];
    const float* w2     = (const float*)d_in[4];
    const float* b2     = (const float*)d_in[5];
    float*       out    = (float*)d_out;

    transpose_w1_kernel<<<dim3((EDIM + 31) / 32, HDIM / 32), dim3(32, 8)>>>(w1);
    gather_mean_kernel<<<BATCH, 96>>>(x, weight);
    mlp_kernel<<<BATCH / ROWS, 256>>>(b1, w2, b2, out);
}